// round 2
// baseline (speedup 1.0000x reference)
#include <cuda_runtime.h>
#include <cuda_bf16.h>
#include <cstdint>

// ---------------- problem dims ----------------
#define BB   8192
#define HH   1024
#define DIN  1024
#define KXH  2048      // concat [x|h] K (per hi/lo half)
#define KS2  4096      // stored K (hi|lo)
#define NG   4096      // 4 gates * H
#define DD1  512
#define DD2  341
#define DD2P 352       // padded to multiple of 32
#define AA   512

// ---------------- scratch (device globals; no allocation allowed) ----------------
__device__ __nv_bfloat16 g_XH2[(size_t)BB * KS2];    // [8192, 2048hi | 2048lo]
__device__ __nv_bfloat16 g_Wcat2[(size_t)NG * KS2];  // [4096, 2048hi | 2048lo]
__device__ float         g_Z[(size_t)BB * NG];       // gate preacts
__device__ __nv_bfloat16 g_hnew[(size_t)BB * HH];
__device__ __nv_bfloat16 g_Wd1[(size_t)DD1 * HH];
__device__ __nv_bfloat16 g_d1[(size_t)BB * DD1];
__device__ __nv_bfloat16 g_Wd2[(size_t)DD2 * DD1];
__device__ __nv_bfloat16 g_d2[(size_t)BB * DD2P];    // cols 341..351 zero
__device__ __nv_bfloat16 g_Wd3[(size_t)AA * DD2P];   // cols 341..351 zero
__device__ float         g_logits[(size_t)BB * AA];

// ---------------- small helpers ----------------
__device__ __forceinline__ void cp_async16(void* smem, const void* gmem, int bytes) {
    uint32_t s = (uint32_t)__cvta_generic_to_shared(smem);
    asm volatile("cp.async.ca.shared.global [%0], [%1], 16, %2;\n"
                 :: "r"(s), "l"(gmem), "r"(bytes));
}
__device__ __forceinline__ void cp_commit() {
    asm volatile("cp.async.commit_group;\n" ::: "memory");
}
__device__ __forceinline__ void ldsm4(uint32_t& r0, uint32_t& r1, uint32_t& r2, uint32_t& r3,
                                      const void* p) {
    uint32_t a = (uint32_t)__cvta_generic_to_shared(p);
    asm volatile("ldmatrix.sync.aligned.m8n8.x4.shared.b16 {%0,%1,%2,%3}, [%4];"
                 : "=r"(r0), "=r"(r1), "=r"(r2), "=r"(r3) : "r"(a));
}
__device__ __forceinline__ void mma16816(float* c, const uint32_t* a, const uint32_t* b) {
    asm volatile("mma.sync.aligned.m16n8k16.row.col.f32.bf16.bf16.f32 "
                 "{%0,%1,%2,%3}, {%4,%5,%6,%7}, {%8,%9}, {%0,%1,%2,%3};"
                 : "+f"(c[0]), "+f"(c[1]), "+f"(c[2]), "+f"(c[3])
                 : "r"(a[0]), "r"(a[1]), "r"(a[2]), "r"(a[3]), "r"(b[0]), "r"(b[1]));
}
__device__ __forceinline__ float sigmoidf_(float x) { return 1.0f / (1.0f + __expf(-x)); }

__device__ __forceinline__ void split_store(__nv_bfloat16* hi, __nv_bfloat16* lo, float v) {
    __nv_bfloat16 h = __float2bfloat16(v);
    *hi = h;
    *lo = __float2bfloat16(v - __bfloat162float(h));
}

// ---------------- prep kernels (fp32 -> split bf16) ----------------
__global__ void k_prep_xh(const float* __restrict__ x, const float* __restrict__ h) {
    int i = blockIdx.x * blockDim.x + threadIdx.x;
    int i4 = i * 4;
    if (i4 >= BB * KXH) return;
    int b = i4 >> 11, k = i4 & 2047;
    const float* src = (k < DIN) ? (x + (size_t)b * DIN + k) : (h + (size_t)b * HH + (k - DIN));
    float4 v = *reinterpret_cast<const float4*>(src);
    __nv_bfloat16* hi = g_XH2 + (size_t)b * KS2 + k;
    __nv_bfloat16* lo = hi + KXH;
    split_store(hi + 0, lo + 0, v.x);
    split_store(hi + 1, lo + 1, v.y);
    split_store(hi + 2, lo + 2, v.z);
    split_store(hi + 3, lo + 3, v.w);
}

__global__ void k_prep_wcat(const float* __restrict__ Wfi, const float* __restrict__ Wfh,
                            const float* __restrict__ Wii, const float* __restrict__ Wih,
                            const float* __restrict__ Wsi, const float* __restrict__ Wsh,
                            const float* __restrict__ Woi, const float* __restrict__ Woh) {
    int i = blockIdx.x * blockDim.x + threadIdx.x;
    int i4 = i * 4;
    if (i4 >= NG * KXH) return;
    int n = i4 >> 11, k = i4 & 2047;
    int g = n >> 10, hr = n & 1023;
    bool second = (k >= 1024);
    int kk = second ? (k - 1024) : k;
    const float* base;
    switch (g) {
        case 0:  base = second ? Wfh : Wfi; break;
        case 1:  base = second ? Wih : Wii; break;
        case 2:  base = second ? Wsh : Wsi; break;
        default: base = second ? Woh : Woi; break;
    }
    float4 v = *reinterpret_cast<const float4*>(base + (size_t)hr * 1024 + kk);
    __nv_bfloat16* hi = g_Wcat2 + (size_t)n * KS2 + k;
    __nv_bfloat16* lo = hi + KXH;
    split_store(hi + 0, lo + 0, v.x);
    split_store(hi + 1, lo + 1, v.y);
    split_store(hi + 2, lo + 2, v.z);
    split_store(hi + 3, lo + 3, v.w);
}

__global__ void k_conv_flat(const float* __restrict__ src, __nv_bfloat16* __restrict__ dst, int n) {
    int i = blockIdx.x * blockDim.x + threadIdx.x;
    int i4 = i * 4;
    if (i4 >= n) return;
    float4 v = *reinterpret_cast<const float4*>(src + i4);
    __nv_bfloat162* d = reinterpret_cast<__nv_bfloat162*>(dst + i4);
    d[0] = __floats2bfloat162_rn(v.x, v.y);
    d[1] = __floats2bfloat162_rn(v.z, v.w);
}

__global__ void k_prep_wd3(const float* __restrict__ W) {  // [512,341] -> [512,352] padded
    int i = blockIdx.x * blockDim.x + threadIdx.x;
    if (i >= AA * DD2P) return;
    int r = i / DD2P, c = i % DD2P;
    g_Wd3[i] = __float2bfloat16((c < DD2) ? W[(size_t)r * DD2 + c] : 0.0f);
}

// ---------------- GEMM: C[M,N] = A[M,K] @ B[N,K]^T (+bias, act), bf16 in / fp32 acc ------------
// 128x128x32 tiles, 256 threads, 8 warps (4 row x 2 col), warp tile 32x64, double-buffered.
// SPLIT3: virtual K = 3*KXH over [hi|lo] storage; A segs {hi,lo,hi}, B segs {hi,hi,lo}.
template <int ACT, bool HASBIAS, bool OUTF32, bool SPLIT3>
__global__ __launch_bounds__(256)
void gemm_bf16(const __nv_bfloat16* __restrict__ Aop, int lda,
               const __nv_bfloat16* __restrict__ Bop, int ldb, int Brows,
               const float* __restrict__ bias,
               float* __restrict__ outF, __nv_bfloat16* __restrict__ outB, int ldc,
               int Nstore, int Nvalid, int K) {
    __shared__ __align__(16) __nv_bfloat16 As[2][128][40];
    __shared__ __align__(16) __nv_bfloat16 Bs[2][128][40];

    const int bm = blockIdx.y * 128;
    const int bn = blockIdx.x * 128;
    const int lane = threadIdx.x & 31;
    const int wid = threadIdx.x >> 5;
    const int wm = (wid & 3) * 32;   // warp row offset in tile
    const int wn = (wid >> 2) * 64;  // warp col offset in tile

    float acc[2][8][4];
#pragma unroll
    for (int mi = 0; mi < 2; mi++)
#pragma unroll
        for (int nj = 0; nj < 8; nj++)
#pragma unroll
            for (int q = 0; q < 4; q++) acc[mi][nj][q] = 0.0f;

    const int r = threadIdx.x >> 2;        // 0..63
    const int ch = (threadIdx.x & 3) * 8;  // halves (16B)

    auto load_tile = [&](int buf, int kt) {
        int akt = kt, bkt = kt;
        if (SPLIT3) {
            // virtual tiles: 0..63 seg0, 64..127 seg1, 128..191 seg2 (64 tiles per 2048-K seg)
            akt = (kt >= 128) ? (kt - 128) : kt;   // A: hi, lo, hi   ([hi|lo] storage)
            bkt = (kt >= 64) ? (kt - 64) : kt;     // B: hi, hi, lo   ([hi|lo] storage)
        }
        int k0a = akt * 32;
        int k0b = bkt * 32;
#pragma unroll
        for (int rr = 0; rr < 2; rr++) {
            int row = r + rr * 64;
            const __nv_bfloat16* srcA = Aop + (size_t)(bm + row) * lda + k0a + ch;
            cp_async16(&As[buf][row][ch], srcA, 16);
        }
#pragma unroll
        for (int rr = 0; rr < 2; rr++) {
            int row = r + rr * 64;
            int gn = bn + row;
            bool ok = gn < Brows;
            const __nv_bfloat16* srcB = Bop + (size_t)(ok ? gn : 0) * ldb + k0b + ch;
            cp_async16(&Bs[buf][row][ch], srcB, ok ? 16 : 0);
        }
    };

    auto compute = [&](int buf) {
#pragma unroll
        for (int ks = 0; ks < 2; ks++) {
            int k0 = ks * 16;
            uint32_t af[2][4];
#pragma unroll
            for (int mi = 0; mi < 2; mi++) {
                int arow = wm + mi * 16 + (lane & 15);
                int acol = k0 + (lane >> 4) * 8;
                ldsm4(af[mi][0], af[mi][1], af[mi][2], af[mi][3], &As[buf][arow][acol]);
            }
            uint32_t bfr[8][2];
#pragma unroll
            for (int nj = 0; nj < 4; nj++) {
                int nrow = wn + nj * 16 + (lane & 7) + ((lane >> 4) << 3);
                int kcol = k0 + ((lane >> 3) & 1) * 8;
                uint32_t r0, r1, r2, r3;
                ldsm4(r0, r1, r2, r3, &Bs[buf][nrow][kcol]);
                bfr[2 * nj][0] = r0; bfr[2 * nj][1] = r1;
                bfr[2 * nj + 1][0] = r2; bfr[2 * nj + 1][1] = r3;
            }
#pragma unroll
            for (int mi = 0; mi < 2; mi++)
#pragma unroll
                for (int nj = 0; nj < 8; nj++)
                    mma16816(acc[mi][nj], af[mi], bfr[nj]);
        }
    };

    const int NT = K / 32;
    load_tile(0, 0);
    cp_commit();
    for (int kt = 0; kt < NT; kt++) {
        if (kt + 1 < NT) {
            load_tile((kt + 1) & 1, kt + 1);
            cp_commit();
            asm volatile("cp.async.wait_group 1;\n" ::: "memory");
        } else {
            asm volatile("cp.async.wait_group 0;\n" ::: "memory");
        }
        __syncthreads();
        compute(kt & 1);
        __syncthreads();
    }

    // epilogue
    const int groupr = lane >> 2;
    const int cc = (lane & 3) * 2;
#pragma unroll
    for (int mi = 0; mi < 2; mi++) {
#pragma unroll
        for (int nj = 0; nj < 8; nj++) {
            int col = bn + wn + nj * 8 + cc;
            if (col >= Nstore) continue;  // Nstore multiple of 8 -> pair-safe
            float b0 = 0.0f, b1 = 0.0f;
            if (HASBIAS) {
                b0 = (col < Nvalid) ? bias[col] : 0.0f;
                b1 = (col + 1 < Nvalid) ? bias[col + 1] : 0.0f;
            }
#pragma unroll
            for (int rr = 0; rr < 2; rr++) {
                int row = bm + wm + mi * 16 + groupr + rr * 8;
                float v0 = acc[mi][nj][rr * 2 + 0] + b0;
                float v1 = acc[mi][nj][rr * 2 + 1] + b1;
                if (ACT == 1) { v0 = tanhf(v0); v1 = tanhf(v1); }
                if (col >= Nvalid) v0 = 0.0f;
                if (col + 1 >= Nvalid) v1 = 0.0f;
                if (OUTF32) {
                    float2* p = reinterpret_cast<float2*>(outF + (size_t)row * ldc + col);
                    *p = make_float2(v0, v1);
                } else {
                    __nv_bfloat162* p =
                        reinterpret_cast<__nv_bfloat162*>(outB + (size_t)row * ldc + col);
                    *p = __floats2bfloat162_rn(v0, v1);
                }
            }
        }
    }
}

// ---------------- LSTM elementwise ----------------
__global__ void k_lstm(const float* __restrict__ c,
                       const float* __restrict__ bfi, const float* __restrict__ bfh,
                       const float* __restrict__ bii, const float* __restrict__ bih,
                       const float* __restrict__ bsi, const float* __restrict__ bsh,
                       const float* __restrict__ boi, const float* __restrict__ boh,
                       float* __restrict__ out) {
    int i = blockIdx.x * blockDim.x + threadIdx.x;
    int i4 = i * 4;
    if (i4 >= BB * HH) return;
    int b = i4 >> 10, u = i4 & 1023;
    const float* Zr = g_Z + (size_t)b * NG;
    float4 zf = *reinterpret_cast<const float4*>(Zr + u);
    float4 zi = *reinterpret_cast<const float4*>(Zr + 1024 + u);
    float4 zs = *reinterpret_cast<const float4*>(Zr + 2048 + u);
    float4 zo = *reinterpret_cast<const float4*>(Zr + 3072 + u);
    float4 cv = *reinterpret_cast<const float4*>(c + i4);
    float4 vfi = *reinterpret_cast<const float4*>(bfi + u);
    float4 vfh = *reinterpret_cast<const float4*>(bfh + u);
    float4 vii = *reinterpret_cast<const float4*>(bii + u);
    float4 vih = *reinterpret_cast<const float4*>(bih + u);
    float4 vsi = *reinterpret_cast<const float4*>(bsi + u);
    float4 vsh = *reinterpret_cast<const float4*>(bsh + u);
    float4 voi = *reinterpret_cast<const float4*>(boi + u);
    float4 voh = *reinterpret_cast<const float4*>(boh + u);

    float hn[4];
    {
        float zfv[4] = {zf.x + vfi.x + vfh.x, zf.y + vfi.y + vfh.y,
                        zf.z + vfi.z + vfh.z, zf.w + vfi.w + vfh.w};
        float ziv[4] = {zi.x + vii.x + vih.x, zi.y + vii.y + vih.y,
                        zi.z + vii.z + vih.z, zi.w + vii.w + vih.w};
        float zsv[4] = {zs.x + vsi.x + vsh.x, zs.y + vsi.y + vsh.y,
                        zs.z + vsi.z + vsh.z, zs.w + vsi.w + vsh.w};
        float zov[4] = {zo.x + voi.x + voh.x, zo.y + voi.y + voh.y,
                        zo.z + voi.z + voh.z, zo.w + voi.w + voh.w};
        float cvv[4] = {cv.x, cv.y, cv.z, cv.w};
#pragma unroll
        for (int q = 0; q < 4; q++) {
            float f = sigmoidf_(zfv[q]);
            float ii = sigmoidf_(ziv[q]);
            float s = tanhf(zsv[q]);
            float o = sigmoidf_(zov[q]);
            float cn = cvv[q] * f + ii * s;
            hn[q] = o * tanhf(cn);
        }
    }
    *reinterpret_cast<float4*>(out + i4) = make_float4(hn[0], hn[1], hn[2], hn[3]);
    __nv_bfloat162* hb = reinterpret_cast<__nv_bfloat162*>(g_hnew + i4);
    hb[0] = __floats2bfloat162_rn(hn[0], hn[1]);
    hb[1] = __floats2bfloat162_rn(hn[2], hn[3]);
}

// ---------------- softmax (one warp per row of 512) ----------------
__global__ void k_softmax(float* __restrict__ out) {
    int row = blockIdx.x * 8 + (threadIdx.x >> 5);
    int lane = threadIdx.x & 31;
    const float* Lr = g_logits + (size_t)row * AA;
    float vals[16];
    float mx = -1e30f;
#pragma unroll
    for (int j = 0; j < 16; j++) {
        vals[j] = Lr[lane + j * 32];
        mx = fmaxf(mx, vals[j]);
    }
#pragma unroll
    for (int off = 16; off > 0; off >>= 1)
        mx = fmaxf(mx, __shfl_xor_sync(0xffffffffu, mx, off));
    float s = 0.0f;
#pragma unroll
    for (int j = 0; j < 16; j++) {
        vals[j] = __expf(vals[j] - mx);
        s += vals[j];
    }
#pragma unroll
    for (int off = 16; off > 0; off >>= 1)
        s += __shfl_xor_sync(0xffffffffu, s, off);
    float inv = 1.0f / s;
    float* orow = out + (size_t)BB * HH + (size_t)row * AA;
#pragma unroll
    for (int j = 0; j < 16; j++) orow[lane + j * 32] = vals[j] * inv;
}

// ---------------- launch ----------------
extern "C" void kernel_launch(void* const* d_in, const int* in_sizes, int n_in,
                              void* d_out, int out_size) {
    const float* x    = (const float*)d_in[0];
    const float* h    = (const float*)d_in[1];
    const float* c    = (const float*)d_in[2];
    const float* W_fi = (const float*)d_in[3];
    const float* b_fi = (const float*)d_in[4];
    const float* W_fh = (const float*)d_in[5];
    const float* b_fh = (const float*)d_in[6];
    const float* W_ii = (const float*)d_in[7];
    const float* b_ii = (const float*)d_in[8];
    const float* W_ih = (const float*)d_in[9];
    const float* b_ih = (const float*)d_in[10];
    const float* W_si = (const float*)d_in[11];
    const float* b_si = (const float*)d_in[12];
    const float* W_sh = (const float*)d_in[13];
    const float* b_sh = (const float*)d_in[14];
    const float* W_oi = (const float*)d_in[15];
    const float* b_oi = (const float*)d_in[16];
    const float* W_oh = (const float*)d_in[17];
    const float* b_oh = (const float*)d_in[18];
    const float* W_d1 = (const float*)d_in[19];
    const float* b_d1 = (const float*)d_in[20];
    const float* W_d2 = (const float*)d_in[21];
    const float* b_d2 = (const float*)d_in[22];
    const float* W_d3 = (const float*)d_in[23];
    const float* b_d3 = (const float*)d_in[24];
    float* out = (float*)d_out;

    __nv_bfloat16 *XH2, *Wcat2, *hnew, *Wd1, *d1, *Wd2, *d2, *Wd3;
    float *Z, *logits;
    cudaGetSymbolAddress((void**)&XH2, g_XH2);
    cudaGetSymbolAddress((void**)&Wcat2, g_Wcat2);
    cudaGetSymbolAddress((void**)&Z, g_Z);
    cudaGetSymbolAddress((void**)&hnew, g_hnew);
    cudaGetSymbolAddress((void**)&Wd1, g_Wd1);
    cudaGetSymbolAddress((void**)&d1, g_d1);
    cudaGetSymbolAddress((void**)&Wd2, g_Wd2);
    cudaGetSymbolAddress((void**)&d2, g_d2);
    cudaGetSymbolAddress((void**)&Wd3, g_Wd3);
    cudaGetSymbolAddress((void**)&logits, g_logits);

    // prep (split bf16 for gates operands; plain bf16 decoder weights)
    k_prep_xh<<<(BB * KXH / 4 + 255) / 256, 256>>>(x, h);
    k_prep_wcat<<<(NG * KXH / 4 + 255) / 256, 256>>>(W_fi, W_fh, W_ii, W_ih, W_si, W_sh, W_oi, W_oh);
    k_conv_flat<<<(DD1 * HH / 4 + 255) / 256, 256>>>(W_d1, Wd1, DD1 * HH);
    k_conv_flat<<<(DD2 * DD1 / 4 + 255) / 256, 256>>>(W_d2, Wd2, DD2 * DD1);
    k_prep_wd3<<<(AA * DD2P + 255) / 256, 256>>>(W_d3);

    // gates GEMM: Z[8192,4096] = XH @ Wcat^T with split-bf16 (virtual K = 6144)
    gemm_bf16<0, false, true, true><<<dim3(NG / 128, BB / 128), 256>>>(
        XH2, KS2, Wcat2, KS2, NG, nullptr, Z, nullptr, NG, NG, NG, 3 * KXH);

    // LSTM elementwise -> out[0:B*H] (h_new fp32) + bf16 copy for decoder
    k_lstm<<<(BB * HH / 4 + 255) / 256, 256>>>(c, b_fi, b_fh, b_ii, b_ih, b_si, b_sh, b_oi, b_oh, out);

    // decoder (plain bf16; error lands only in low-norm softmax block)
    gemm_bf16<1, true, false, false><<<dim3(DD1 / 128, BB / 128), 256>>>(
        hnew, HH, Wd1, HH, DD1, b_d1, nullptr, d1, DD1, DD1, DD1, HH);
    gemm_bf16<1, true, false, false><<<dim3((DD2P + 127) / 128, BB / 128), 256>>>(
        d1, DD1, Wd2, DD1, DD2, b_d2, nullptr, d2, DD2P, DD2P, DD2, DD1);
    gemm_bf16<0, true, true, false><<<dim3(AA / 128, BB / 128), 256>>>(
        d2, DD2P, Wd3, DD2P, AA, b_d3, logits, nullptr, AA, AA, AA, DD2P);

    // softmax -> out[B*H:]
    k_softmax<<<BB / 8, 256>>>(out);
}

// round 3
// speedup vs baseline: 2.5466x; 2.5466x over previous
#include <cuda_runtime.h>
#include <cuda_fp16.h>
#include <cstdint>

// ---------------- problem dims ----------------
#define BB   8192
#define HH   1024
#define DIN  1024
#define KXH  2048      // concat [x|h] K
#define NG   4096      // 4 gates * H
#define DD1  512
#define DD2  341
#define DD2P 352       // padded to multiple of 32
#define AA   512

// ---------------- scratch (device globals; no allocation allowed) ----------------
__device__ __half g_XH[(size_t)BB * KXH];     // [8192,2048]
__device__ __half g_Wcat[(size_t)NG * KXH];   // [4096,2048]  rows: f,i,s,o
__device__ float  g_Z[(size_t)BB * NG];       // gate preacts
__device__ __half g_hnew[(size_t)BB * HH];
__device__ __half g_Wd1[(size_t)DD1 * HH];
__device__ __half g_d1[(size_t)BB * DD1];
__device__ __half g_Wd2[(size_t)DD2 * DD1];
__device__ __half g_d2[(size_t)BB * DD2P];    // cols 341..351 zero
__device__ __half g_Wd3[(size_t)AA * DD2P];   // cols 341..351 zero
__device__ float  g_logits[(size_t)BB * AA];

// ---------------- small helpers ----------------
__device__ __forceinline__ void cp_async16(void* smem, const void* gmem, int bytes) {
    uint32_t s = (uint32_t)__cvta_generic_to_shared(smem);
    asm volatile("cp.async.ca.shared.global [%0], [%1], 16, %2;\n"
                 :: "r"(s), "l"(gmem), "r"(bytes));
}
__device__ __forceinline__ void cp_commit() {
    asm volatile("cp.async.commit_group;\n" ::: "memory");
}
__device__ __forceinline__ void ldsm4(uint32_t& r0, uint32_t& r1, uint32_t& r2, uint32_t& r3,
                                      const void* p) {
    uint32_t a = (uint32_t)__cvta_generic_to_shared(p);
    asm volatile("ldmatrix.sync.aligned.m8n8.x4.shared.b16 {%0,%1,%2,%3}, [%4];"
                 : "=r"(r0), "=r"(r1), "=r"(r2), "=r"(r3) : "r"(a));
}
__device__ __forceinline__ void mma16816(float* c, const uint32_t* a, const uint32_t* b) {
    asm volatile("mma.sync.aligned.m16n8k16.row.col.f32.f16.f16.f32 "
                 "{%0,%1,%2,%3}, {%4,%5,%6,%7}, {%8,%9}, {%0,%1,%2,%3};"
                 : "+f"(c[0]), "+f"(c[1]), "+f"(c[2]), "+f"(c[3])
                 : "r"(a[0]), "r"(a[1]), "r"(a[2]), "r"(a[3]), "r"(b[0]), "r"(b[1]));
}
__device__ __forceinline__ float sigmoidf_(float x) { return 1.0f / (1.0f + __expf(-x)); }

// ---------------- prep kernels (fp32 -> fp16) ----------------
__global__ void k_prep_xh(const float* __restrict__ x, const float* __restrict__ h) {
    int i = blockIdx.x * blockDim.x + threadIdx.x;
    int i4 = i * 4;
    if (i4 >= BB * KXH) return;
    int b = i4 >> 11, k = i4 & 2047;
    const float* src = (k < DIN) ? (x + (size_t)b * DIN + k) : (h + (size_t)b * HH + (k - DIN));
    float4 v = *reinterpret_cast<const float4*>(src);
    __half2* dst = reinterpret_cast<__half2*>(g_XH + i4);
    dst[0] = __floats2half2_rn(v.x, v.y);
    dst[1] = __floats2half2_rn(v.z, v.w);
}

__global__ void k_prep_wcat(const float* __restrict__ Wfi, const float* __restrict__ Wfh,
                            const float* __restrict__ Wii, const float* __restrict__ Wih,
                            const float* __restrict__ Wsi, const float* __restrict__ Wsh,
                            const float* __restrict__ Woi, const float* __restrict__ Woh) {
    int i = blockIdx.x * blockDim.x + threadIdx.x;
    int i4 = i * 4;
    if (i4 >= NG * KXH) return;
    int n = i4 >> 11, k = i4 & 2047;
    int g = n >> 10, hr = n & 1023;
    bool second = (k >= 1024);
    int kk = second ? (k - 1024) : k;
    const float* base;
    switch (g) {
        case 0:  base = second ? Wfh : Wfi; break;
        case 1:  base = second ? Wih : Wii; break;
        case 2:  base = second ? Wsh : Wsi; break;
        default: base = second ? Woh : Woi; break;
    }
    float4 v = *reinterpret_cast<const float4*>(base + (size_t)hr * 1024 + kk);
    __half2* dst = reinterpret_cast<__half2*>(g_Wcat + i4);
    dst[0] = __floats2half2_rn(v.x, v.y);
    dst[1] = __floats2half2_rn(v.z, v.w);
}

__global__ void k_conv_flat(const float* __restrict__ src, __half* __restrict__ dst, int n) {
    int i = blockIdx.x * blockDim.x + threadIdx.x;
    int i4 = i * 4;
    if (i4 >= n) return;
    float4 v = *reinterpret_cast<const float4*>(src + i4);
    __half2* d = reinterpret_cast<__half2*>(dst + i4);
    d[0] = __floats2half2_rn(v.x, v.y);
    d[1] = __floats2half2_rn(v.z, v.w);
}

__global__ void k_prep_wd3(const float* __restrict__ W) {  // [512,341] -> [512,352] padded
    int i = blockIdx.x * blockDim.x + threadIdx.x;
    if (i >= AA * DD2P) return;
    int r = i / DD2P, c = i % DD2P;
    g_Wd3[i] = __float2half((c < DD2) ? W[(size_t)r * DD2 + c] : 0.0f);
}

// ---------------- GEMM: C[M,N] = A[M,K] @ B[N,K]^T (+bias, act), fp16 in / fp32 acc ------------
// 128x128x32 tiles, 256 threads, 8 warps (4 row x 2 col), warp tile 32x64.
// 3-stage cp.async pipeline, ONE __syncthreads per k-tile.
template <int ACT, bool HASBIAS, bool OUTF32>
__global__ __launch_bounds__(256)
void gemm_fp16(const __half* __restrict__ Aop, int lda,
               const __half* __restrict__ Bop, int ldb, int Brows,
               const float* __restrict__ bias,
               float* __restrict__ outF, __half* __restrict__ outB, int ldc,
               int Nstore, int Nvalid, int K) {
    __shared__ __align__(16) __half As[3][128][40];
    __shared__ __align__(16) __half Bs[3][128][40];

    const int bm = blockIdx.y * 128;
    const int bn = blockIdx.x * 128;
    const int lane = threadIdx.x & 31;
    const int wid = threadIdx.x >> 5;
    const int wm = (wid & 3) * 32;   // warp row offset in tile
    const int wn = (wid >> 2) * 64;  // warp col offset in tile

    float acc[2][8][4];
#pragma unroll
    for (int mi = 0; mi < 2; mi++)
#pragma unroll
        for (int nj = 0; nj < 8; nj++)
#pragma unroll
            for (int q = 0; q < 4; q++) acc[mi][nj][q] = 0.0f;

    const int r = threadIdx.x >> 2;        // 0..63
    const int ch = (threadIdx.x & 3) * 8;  // halves (16B)

    auto load_tile = [&](int buf, int kt) {
        int k0 = kt * 32;
#pragma unroll
        for (int rr = 0; rr < 2; rr++) {
            int row = r + rr * 64;
            const __half* srcA = Aop + (size_t)(bm + row) * lda + k0 + ch;
            cp_async16(&As[buf][row][ch], srcA, 16);
        }
#pragma unroll
        for (int rr = 0; rr < 2; rr++) {
            int row = r + rr * 64;
            int gn = bn + row;
            bool ok = gn < Brows;
            const __half* srcB = Bop + (size_t)(ok ? gn : 0) * ldb + k0 + ch;
            cp_async16(&Bs[buf][row][ch], srcB, ok ? 16 : 0);
        }
    };

    auto compute = [&](int buf) {
#pragma unroll
        for (int ks = 0; ks < 2; ks++) {
            int k0 = ks * 16;
            uint32_t af[2][4];
#pragma unroll
            for (int mi = 0; mi < 2; mi++) {
                int arow = wm + mi * 16 + (lane & 15);
                int acol = k0 + (lane >> 4) * 8;
                ldsm4(af[mi][0], af[mi][1], af[mi][2], af[mi][3], &As[buf][arow][acol]);
            }
            uint32_t bfr[8][2];
#pragma unroll
            for (int nj = 0; nj < 4; nj++) {
                int nrow = wn + nj * 16 + (lane & 7) + ((lane >> 4) << 3);
                int kcol = k0 + ((lane >> 3) & 1) * 8;
                uint32_t r0, r1, r2, r3;
                ldsm4(r0, r1, r2, r3, &Bs[buf][nrow][kcol]);
                bfr[2 * nj][0] = r0; bfr[2 * nj][1] = r1;
                bfr[2 * nj + 1][0] = r2; bfr[2 * nj + 1][1] = r3;
            }
#pragma unroll
            for (int mi = 0; mi < 2; mi++)
#pragma unroll
                for (int nj = 0; nj < 8; nj++)
                    mma16816(acc[mi][nj], af[mi], bfr[nj]);
        }
    };

    const int NT = K / 32;
    load_tile(0, 0);
    cp_commit();
    load_tile(1, 1);
    cp_commit();
    int buf = 0;
    for (int kt = 0; kt < NT; kt++) {
        asm volatile("cp.async.wait_group 1;\n" ::: "memory");
        __syncthreads();
        if (kt + 2 < NT) {
            load_tile((buf + 2) % 3, kt + 2);
            cp_commit();
        } else {
            cp_commit();  // keep group-count accounting uniform
        }
        compute(buf);
        buf = (buf + 1) % 3;
    }

    // epilogue
    const int groupr = lane >> 2;
    const int cc = (lane & 3) * 2;
#pragma unroll
    for (int mi = 0; mi < 2; mi++) {
#pragma unroll
        for (int nj = 0; nj < 8; nj++) {
            int col = bn + wn + nj * 8 + cc;
            if (col >= Nstore) continue;  // Nstore multiple of 8 -> pair-safe
            float b0 = 0.0f, b1 = 0.0f;
            if (HASBIAS) {
                b0 = (col < Nvalid) ? bias[col] : 0.0f;
                b1 = (col + 1 < Nvalid) ? bias[col + 1] : 0.0f;
            }
#pragma unroll
            for (int rr = 0; rr < 2; rr++) {
                int row = bm + wm + mi * 16 + groupr + rr * 8;
                float v0 = acc[mi][nj][rr * 2 + 0] + b0;
                float v1 = acc[mi][nj][rr * 2 + 1] + b1;
                if (ACT == 1) { v0 = tanhf(v0); v1 = tanhf(v1); }
                if (col >= Nvalid) v0 = 0.0f;
                if (col + 1 >= Nvalid) v1 = 0.0f;
                if (OUTF32) {
                    float2* p = reinterpret_cast<float2*>(outF + (size_t)row * ldc + col);
                    *p = make_float2(v0, v1);
                } else {
                    __half2* p = reinterpret_cast<__half2*>(outB + (size_t)row * ldc + col);
                    *p = __floats2half2_rn(v0, v1);
                }
            }
        }
    }
}

// ---------------- LSTM elementwise ----------------
__global__ void k_lstm(const float* __restrict__ c,
                       const float* __restrict__ bfi, const float* __restrict__ bfh,
                       const float* __restrict__ bii, const float* __restrict__ bih,
                       const float* __restrict__ bsi, const float* __restrict__ bsh,
                       const float* __restrict__ boi, const float* __restrict__ boh,
                       float* __restrict__ out) {
    int i = blockIdx.x * blockDim.x + threadIdx.x;
    int i4 = i * 4;
    if (i4 >= BB * HH) return;
    int b = i4 >> 10, u = i4 & 1023;
    const float* Zr = g_Z + (size_t)b * NG;
    float4 zf = *reinterpret_cast<const float4*>(Zr + u);
    float4 zi = *reinterpret_cast<const float4*>(Zr + 1024 + u);
    float4 zs = *reinterpret_cast<const float4*>(Zr + 2048 + u);
    float4 zo = *reinterpret_cast<const float4*>(Zr + 3072 + u);
    float4 cv = *reinterpret_cast<const float4*>(c + i4);
    float4 vfi = *reinterpret_cast<const float4*>(bfi + u);
    float4 vfh = *reinterpret_cast<const float4*>(bfh + u);
    float4 vii = *reinterpret_cast<const float4*>(bii + u);
    float4 vih = *reinterpret_cast<const float4*>(bih + u);
    float4 vsi = *reinterpret_cast<const float4*>(bsi + u);
    float4 vsh = *reinterpret_cast<const float4*>(bsh + u);
    float4 voi = *reinterpret_cast<const float4*>(boi + u);
    float4 voh = *reinterpret_cast<const float4*>(boh + u);

    float hn[4];
    {
        float zfv[4] = {zf.x + vfi.x + vfh.x, zf.y + vfi.y + vfh.y,
                        zf.z + vfi.z + vfh.z, zf.w + vfi.w + vfh.w};
        float ziv[4] = {zi.x + vii.x + vih.x, zi.y + vii.y + vih.y,
                        zi.z + vii.z + vih.z, zi.w + vii.w + vih.w};
        float zsv[4] = {zs.x + vsi.x + vsh.x, zs.y + vsi.y + vsh.y,
                        zs.z + vsi.z + vsh.z, zs.w + vsi.w + vsh.w};
        float zov[4] = {zo.x + voi.x + voh.x, zo.y + voi.y + voh.y,
                        zo.z + voi.z + voh.z, zo.w + voi.w + voh.w};
        float cvv[4] = {cv.x, cv.y, cv.z, cv.w};
#pragma unroll
        for (int q = 0; q < 4; q++) {
            float f = sigmoidf_(zfv[q]);
            float ii = sigmoidf_(ziv[q]);
            float s = tanhf(zsv[q]);
            float o = sigmoidf_(zov[q]);
            float cn = cvv[q] * f + ii * s;
            hn[q] = o * tanhf(cn);
        }
    }
    *reinterpret_cast<float4*>(out + i4) = make_float4(hn[0], hn[1], hn[2], hn[3]);
    __half2* hb = reinterpret_cast<__half2*>(g_hnew + i4);
    hb[0] = __floats2half2_rn(hn[0], hn[1]);
    hb[1] = __floats2half2_rn(hn[2], hn[3]);
}

// ---------------- softmax (one warp per row of 512) ----------------
__global__ void k_softmax(float* __restrict__ out) {
    int row = blockIdx.x * 8 + (threadIdx.x >> 5);
    int lane = threadIdx.x & 31;
    const float* Lr = g_logits + (size_t)row * AA;
    float vals[16];
    float mx = -1e30f;
#pragma unroll
    for (int j = 0; j < 16; j++) {
        vals[j] = Lr[lane + j * 32];
        mx = fmaxf(mx, vals[j]);
    }
#pragma unroll
    for (int off = 16; off > 0; off >>= 1)
        mx = fmaxf(mx, __shfl_xor_sync(0xffffffffu, mx, off));
    float s = 0.0f;
#pragma unroll
    for (int j = 0; j < 16; j++) {
        vals[j] = __expf(vals[j] - mx);
        s += vals[j];
    }
#pragma unroll
    for (int off = 16; off > 0; off >>= 1)
        s += __shfl_xor_sync(0xffffffffu, s, off);
    float inv = 1.0f / s;
    float* orow = out + (size_t)BB * HH + (size_t)row * AA;
#pragma unroll
    for (int j = 0; j < 16; j++) orow[lane + j * 32] = vals[j] * inv;
}

// ---------------- launch ----------------
extern "C" void kernel_launch(void* const* d_in, const int* in_sizes, int n_in,
                              void* d_out, int out_size) {
    const float* x    = (const float*)d_in[0];
    const float* h    = (const float*)d_in[1];
    const float* c    = (const float*)d_in[2];
    const float* W_fi = (const float*)d_in[3];
    const float* b_fi = (const float*)d_in[4];
    const float* W_fh = (const float*)d_in[5];
    const float* b_fh = (const float*)d_in[6];
    const float* W_ii = (const float*)d_in[7];
    const float* b_ii = (const float*)d_in[8];
    const float* W_ih = (const float*)d_in[9];
    const float* b_ih = (const float*)d_in[10];
    const float* W_si = (const float*)d_in[11];
    const float* b_si = (const float*)d_in[12];
    const float* W_sh = (const float*)d_in[13];
    const float* b_sh = (const float*)d_in[14];
    const float* W_oi = (const float*)d_in[15];
    const float* b_oi = (const float*)d_in[16];
    const float* W_oh = (const float*)d_in[17];
    const float* b_oh = (const float*)d_in[18];
    const float* W_d1 = (const float*)d_in[19];
    const float* b_d1 = (const float*)d_in[20];
    const float* W_d2 = (const float*)d_in[21];
    const float* b_d2 = (const float*)d_in[22];
    const float* W_d3 = (const float*)d_in[23];
    const float* b_d3 = (const float*)d_in[24];
    float* out = (float*)d_out;

    __half *XH, *Wcat, *hnew, *Wd1, *d1, *Wd2, *d2, *Wd3;
    float *Z, *logits;
    cudaGetSymbolAddress((void**)&XH, g_XH);
    cudaGetSymbolAddress((void**)&Wcat, g_Wcat);
    cudaGetSymbolAddress((void**)&Z, g_Z);
    cudaGetSymbolAddress((void**)&hnew, g_hnew);
    cudaGetSymbolAddress((void**)&Wd1, g_Wd1);
    cudaGetSymbolAddress((void**)&d1, g_d1);
    cudaGetSymbolAddress((void**)&Wd2, g_Wd2);
    cudaGetSymbolAddress((void**)&d2, g_d2);
    cudaGetSymbolAddress((void**)&Wd3, g_Wd3);
    cudaGetSymbolAddress((void**)&logits, g_logits);

    // prep (fp32 -> fp16)
    k_prep_xh<<<(BB * KXH / 4 + 255) / 256, 256>>>(x, h);
    k_prep_wcat<<<(NG * KXH / 4 + 255) / 256, 256>>>(W_fi, W_fh, W_ii, W_ih, W_si, W_sh, W_oi, W_oh);
    k_conv_flat<<<(DD1 * HH / 4 + 255) / 256, 256>>>(W_d1, Wd1, DD1 * HH);
    k_conv_flat<<<(DD2 * DD1 / 4 + 255) / 256, 256>>>(W_d2, Wd2, DD2 * DD1);
    k_prep_wd3<<<(AA * DD2P + 255) / 256, 256>>>(W_d3);

    // gates GEMM: Z[8192,4096] = XH @ Wcat^T  (single fp16 pass, K=2048)
    gemm_fp16<0, false, true><<<dim3(NG / 128, BB / 128), 256>>>(
        XH, KXH, Wcat, KXH, NG, nullptr, Z, nullptr, NG, NG, NG, KXH);

    // LSTM elementwise -> out[0:B*H] (h_new fp32) + fp16 copy for decoder
    k_lstm<<<(BB * HH / 4 + 255) / 256, 256>>>(c, b_fi, b_fh, b_ii, b_ih, b_si, b_sh, b_oi, b_oh, out);

    // decoder (fp16)
    gemm_fp16<1, true, false><<<dim3(DD1 / 128, BB / 128), 256>>>(
        hnew, HH, Wd1, HH, DD1, b_d1, nullptr, d1, DD1, DD1, DD1, HH);
    gemm_fp16<1, true, false><<<dim3((DD2P + 127) / 128, BB / 128), 256>>>(
        d1, DD1, Wd2, DD1, DD2, b_d2, nullptr, d2, DD2P, DD2P, DD2, DD1);
    gemm_fp16<0, true, true><<<dim3(AA / 128, BB / 128), 256>>>(
        d2, DD2P, Wd3, DD2P, AA, b_d3, logits, nullptr, AA, AA, AA, DD2P);

    // softmax -> out[B*H:]
    k_softmax<<<BB / 8, 256>>>(out);
}